// round 14
// baseline (speedup 1.0000x reference)
#include <cuda_runtime.h>
#include <cuda_fp16.h>
#include <cstdint>
#include <math.h>

// ============================================================================
// Globals
// ============================================================================

__device__ double g_sum[2];

// fp16 panels (pre-scaled by sqrt(log2e)), [tb = t*4+b][pos][c] layout:
#define L0_OFF 0
#define L1_OFF 2097152
__device__ __half g_scratch[3145728];

// ============================================================================
// Pre-convert: fp32 [b][c][pos] -> fp16 panel [tb][pos][C], scaled by
// sqrt(log2e) so the Gram arrives pre-multiplied by log2(e): softmax exp
// becomes a raw ex2.  (convert<64> also zeroes the global sums.)
// ============================================================================
#define SQRT_LOG2E 1.2011224087f

template <int C>
__global__ void __launch_bounds__(256)
convert_kernel(const float* __restrict__ f1, const float* __restrict__ f2,
               int HW, int off, int do_init)
{
    if (do_init && blockIdx.x == 0 && blockIdx.y == 0 && blockIdx.z == 0 &&
        threadIdx.x == 0) {
        g_sum[0] = 0.0; g_sum[1] = 0.0;
    }
    __shared__ float tile[C * 65];  // [c][pos0..63], padded
    const int t = blockIdx.z, b = blockIdx.y;
    const int pos0 = blockIdx.x * 64;
    const float* src = (t ? f2 : f1) + (size_t)b * C * HW;

    for (int idx = threadIdx.x; idx < C * 64; idx += 256) {
        int c = idx >> 6, p = idx & 63;
        tile[c * 65 + p] = src[(size_t)c * HW + pos0 + p];
    }
    __syncthreads();

    __half* o = g_scratch + off + ((size_t)(t * 4 + b) * HW + pos0) * C;
    constexpr int CSH = (C == 64) ? 6 : 7;
    for (int idx = threadIdx.x; idx < 64 * C; idx += 256) {
        int p = idx >> CSH, c = idx & (C - 1);
        o[(size_t)p * C + c] = __float2half(tile[c * 65 + p] * SQRT_LOG2E);
    }
}

// ============================================================================
// PTX helpers (sm_80+ vocabulary only)
// ============================================================================

__device__ __forceinline__ uint32_t smem_to_u32(const void* p) {
    uint32_t a;
    asm("{ .reg .u64 t; cvta.to.shared.u64 t, %1; cvt.u32.u64 %0, t; }"
        : "=r"(a) : "l"(p));
    return a;
}

__device__ __forceinline__ void ldmatrix_x4(uint32_t* r, uint32_t addr) {
    asm volatile(
        "ldmatrix.sync.aligned.m8n8.x4.shared.b16 {%0,%1,%2,%3}, [%4];"
        : "=r"(r[0]), "=r"(r[1]), "=r"(r[2]), "=r"(r[3]) : "r"(addr));
}

// fp16-accumulate MMA: D (2 regs of half2) += A @ B^T
__device__ __forceinline__ void mma_16816_h(uint32_t* d, const uint32_t* a,
                                            const uint32_t* b) {
    asm volatile(
        "mma.sync.aligned.m16n8k16.row.col.f16.f16.f16.f16 "
        "{%0,%1}, {%2,%3,%4,%5}, {%6,%7}, {%0,%1};"
        : "+r"(d[0]), "+r"(d[1])
        : "r"(a[0]), "r"(a[1]), "r"(a[2]), "r"(a[3]), "r"(b[0]), "r"(b[1]));
}

__device__ __forceinline__ void cp_async16(uint32_t saddr, const void* gaddr) {
    asm volatile("cp.async.cg.shared.global [%0], [%1], 16;"
                 :: "r"(saddr), "l"(gaddr));
}
#define CP_COMMIT() asm volatile("cp.async.commit_group;" ::: "memory")
#define CP_WAIT(n)  asm volatile("cp.async.wait_group %0;" :: "n"(n) : "memory")

__device__ __forceinline__ __half2 u2h(uint32_t v) {
    return *reinterpret_cast<__half2*>(&v);
}
__device__ __forceinline__ uint32_t h2u(__half2 v) {
    return *reinterpret_cast<uint32_t*>(&v);
}

// single-instruction f16x2 2^x
__device__ __forceinline__ __half2 ex2_h2(__half2 x) {
    uint32_t r, xi = h2u(x);
    asm("ex2.approx.f16x2 %0, %1;" : "=r"(r) : "r"(xi));
    return u2h(r);
}

// fast per-element reciprocal of a half2 via 2x rcp.approx.f32
__device__ __forceinline__ __half2 rcp_h2(__half2 s) {
    float lo = __low2float(s), hi = __high2float(s);
    float rlo, rhi;
    asm("rcp.approx.f32 %0, %1;" : "=f"(rlo) : "f"(lo));
    asm("rcp.approx.f32 %0, %1;" : "=f"(rhi) : "f"(hi));
    return __floats2half2_rn(rlo, rhi);
}

// ============================================================================
// Fused Gram (mma.sync fp16 acc) + two-phase f16x2 batch-softmax + |diff|.
// Block: 128(i) x 64(j) tile; grid (tj, ti) with early-exit when tj < 2*ti.
// 512 threads = 16 warps (8 row x 2 col), warp = 16m x 32n.
// acc = 8 half2 regs per batch; 1 CTA/SM (reg cap 128, no spills).
// ============================================================================
template <int C, int NSTAGES>
__global__ void __launch_bounds__(512, 1)
gram_loss_mma(int HW, int off, int level)
{
    const int ti = blockIdx.y, tj = blockIdx.x;
    if (tj < 2 * ti) return;  // tile entirely below diagonal

    constexpr int NCH = C / 8;                 // 16B chunks per row
    constexpr int KBS = C / 64;                // k-blocks
    constexpr int A_TILE = KBS * 16384;        // 128 rows
    constexpr int B_TILE = KBS * 8192;         // 64 rows
    constexpr int STAGE_B = A_TILE + B_TILE;
    constexpr int KSTEPS = C / 16;
    constexpr int NLA = 128 * NCH / 512;       // A cp.async iters per thread
    constexpr int NLB = 64 * NCH / 512;        // B cp.async iters per thread

    extern __shared__ char smem[];
    const uint32_t sb = smem_to_u32(smem);
    uint32_t* aff = (uint32_t*)(smem + NSTAGES * STAGE_B);  // [b*8+r][512] 64 KB

    const int tid = threadIdx.x, wid = tid >> 5, lid = tid & 31;
    const int wrow = wid & 7, wcol = wid >> 3;   // 8x2 warp grid
    const int i0 = ti * 128, j0 = tj * 64;

    // ---- precomputed loader offsets (combo/stage-invariant) ----
    uint32_t la_sm[NLA], la_gl[NLA];
    #pragma unroll
    for (int p = 0; p < NLA; ++p) {
        const int v = p * 512 + tid;
        const int row = v / NCH, kcq = v % NCH;
        la_sm[p] = (kcq >> 3) * 16384 + row * 128 +
                   (((kcq & 7) ^ (row & 7)) << 4);
        la_gl[p] = row * C + kcq * 8;
    }
    uint32_t lb_sm[NLB], lb_gl[NLB];
    #pragma unroll
    for (int p = 0; p < NLB; ++p) {
        const int v = p * 512 + tid;
        const int row = v / NCH, kcq = v % NCH;
        lb_sm[p] = A_TILE + (kcq >> 3) * 8192 + row * 128 +
                   (((kcq & 7) ^ (row & 7)) << 4);
        lb_gl[p] = row * C + kcq * 8;
    }

    const size_t HWC = (size_t)HW * C;
    auto load_stage = [&](int combo, int stage) {
        const __half* base = g_scratch + off + (size_t)combo * HWC;
        const __half* sA = base + (size_t)i0 * C;
        const __half* sB = base + (size_t)j0 * C;
        const uint32_t stb = sb + stage * STAGE_B;
        #pragma unroll
        for (int p = 0; p < NLA; ++p) cp_async16(stb + la_sm[p], sA + la_gl[p]);
        #pragma unroll
        for (int p = 0; p < NLB; ++p) cp_async16(stb + lb_sm[p], sB + lb_gl[p]);
    };

    // ---- per-lane ldmatrix addressing (stage-invariant) ----
    const int mat = lid >> 3, lrow = lid & 7;
    const int a_row = wrow * 16 + ((mat & 1) << 3) + lrow;
    const int a_kh = mat >> 1;
    const int b_row0 = wcol * 32 + ((mat >> 1) << 3) + lrow;
    const int b_row1 = b_row0 + 16;
    const int b_kh = mat & 1;
    const uint32_t a_off  = a_row * 128;
    const uint32_t b_off0 = A_TILE + b_row0 * 128;
    const uint32_t b_off1 = A_TILE + b_row1 * 128;
    const int a_r7 = a_row & 7, b_r70 = b_row0 & 7, b_r71 = b_row1 & 7;

    load_stage(0, 0); CP_COMMIT();
    load_stage(1, 1); CP_COMMIT();

    // acc[b][r]: r = mi*2 + dreg; mi: 0=(h0,nb0) 1=(h0,nb1) 2=(h1,nb0) 3=(h1,nb1)
    // dreg 0 -> row gi, 1 -> row gi+8; each reg = half2 over cols (j, j+1)
    uint32_t acc[4][8];
    float wsum = 0.0f;
    const bool fullabove = (tj >= 2 * ti + 2);
    const int gi = lid >> 2, gj = (lid & 3) << 1;

    #pragma unroll 1
    for (int t = 0; t < 2; ++t) {
        #pragma unroll
        for (int b = 0; b < 4; ++b) {
            const int combo = t * 4 + b;
            if (combo == 7) { CP_WAIT(0); } else { CP_WAIT(1); }
            __syncthreads();  // combo's stage ready; prior readers done
            if (combo + 2 < 8) {
                load_stage(combo + 2, (combo + 2) % NSTAGES);
                CP_COMMIT();
            }

            const uint32_t stb = sb + (combo % NSTAGES) * STAGE_B;
            #pragma unroll
            for (int s = 0; s < 8; ++s) acc[b][s] = 0u;

            #pragma unroll
            for (int ks = 0; ks < KSTEPS; ++ks) {
                const int kb = ks >> 2, kc = (ks & 3) * 2;
                uint32_t af[4], b0[4], b1[4];
                ldmatrix_x4(af, stb + a_off  + kb * 16384 +
                                (((kc + a_kh) ^ a_r7)  << 4));
                ldmatrix_x4(b0, stb + b_off0 + kb * 8192 +
                                (((kc + b_kh) ^ b_r70) << 4));
                ldmatrix_x4(b1, stb + b_off1 + kb * 8192 +
                                (((kc + b_kh) ^ b_r71) << 4));
                mma_16816_h(acc[b] + 0, af, b0 + 0);   // h0 nb0 -> r0,r1
                mma_16816_h(acc[b] + 2, af, b0 + 2);   // h0 nb1 -> r2,r3
                mma_16816_h(acc[b] + 4, af, b1 + 0);   // h1 nb0 -> r4,r5
                mma_16816_h(acc[b] + 6, af, b1 + 2);   // h1 nb1 -> r6,r7
            }
        }

        // ---- per-phase f16x2 epilogue: base-2 softmax + |diff| ----
        #pragma unroll
        for (int r = 0; r < 8; ++r) {
            const __half2 A0 = u2h(acc[0][r]), A1 = u2h(acc[1][r]);
            const __half2 A2 = u2h(acc[2][r]), A3 = u2h(acc[3][r]);
            const __half2 m = __hmax2(__hmax2(A0, A1), __hmax2(A2, A3));
            const __half2 e0 = ex2_h2(__hsub2(A0, m));
            const __half2 e1 = ex2_h2(__hsub2(A1, m));
            const __half2 e2 = ex2_h2(__hsub2(A2, m));
            const __half2 e3 = ex2_h2(__hsub2(A3, m));
            const __half2 sum = __hadd2(__hadd2(e0, e1), __hadd2(e2, e3));
            const __half2 inv = rcp_h2(sum);
            const __half2 p0 = __hmul2(e0, inv), p1 = __hmul2(e1, inv);
            const __half2 p2 = __hmul2(e2, inv), p3 = __hmul2(e3, inv);

            if (t == 0) {
                aff[(0 * 8 + r) * 512 + tid] = h2u(p0);
                aff[(1 * 8 + r) * 512 + tid] = h2u(p1);
                aff[(2 * 8 + r) * 512 + tid] = h2u(p2);
                aff[(3 * 8 + r) * 512 + tid] = h2u(p3);
            } else {
                __half2 d = __habs2(__hsub2(u2h(aff[(0*8+r)*512 + tid]), p0));
                d = __hadd2(d, __habs2(__hsub2(u2h(aff[(1*8+r)*512 + tid]), p1)));
                d = __hadd2(d, __habs2(__hsub2(u2h(aff[(2*8+r)*512 + tid]), p2)));
                d = __hadd2(d, __habs2(__hsub2(u2h(aff[(3*8+r)*512 + tid]), p3)));
                const float2 dd = __half22float2(d);
                if (fullabove) {
                    wsum += dd.x + dd.y;
                } else {
                    const int mi = r >> 1;
                    const int i = i0 + wrow * 16 + gi + ((r & 1) << 3);
                    const int j = j0 + wcol * 32 + ((mi >> 1) << 4)
                                + ((mi & 1) << 3) + gj;
                    const float wlo = (j > i) ? 2.0f : ((j == i) ? 1.0f : 0.0f);
                    const float whi = (j + 1 > i) ? 2.0f : ((j + 1 == i) ? 1.0f : 0.0f);
                    wsum += wlo * dd.x + whi * dd.y;
                }
            }
        }
    }

    // ---- reduce: warp shfl -> smem -> single atomic ----
    if (fullabove) wsum *= 2.0f;
    #pragma unroll
    for (int s2 = 16; s2; s2 >>= 1) wsum += __shfl_xor_sync(0xFFFFFFFFu, wsum, s2);
    __syncthreads();
    float* wsums = (float*)smem;
    if (lid == 0) wsums[wid] = wsum;
    __syncthreads();
    if (tid == 0) {
        float tt = 0.0f;
        #pragma unroll
        for (int wq = 0; wq < 16; ++wq) tt += wsums[wq];
        atomicAdd(&g_sum[level], (double)tt);
    }
}

__global__ void finalize_kernel(float* out) {
    const double n0 = 4.0 * 4096.0 * 4096.0;
    const double n1 = 4.0 * 1024.0 * 1024.0;
    out[0] = (float)((g_sum[0] / n0 + g_sum[1] / n1) * 0.5);
}

// ============================================================================
// Launch
// ============================================================================
extern "C" void kernel_launch(void* const* d_in, const int* in_sizes, int n_in,
                              void* d_out, int out_size)
{
    const float* fea1_0 = (const float*)d_in[0];  // (4, 64, 64, 64)
    const float* fea1_1 = (const float*)d_in[1];  // (4, 128, 32, 32)
    const float* fea2_0 = (const float*)d_in[2];
    const float* fea2_1 = (const float*)d_in[3];
    float* out = (float*)d_out;

    // smem: NSTAGES * stage + 64KB aff buffer (1 CTA/SM both levels)
    const int smem0 = 3 * 24576 + 65536;    // C=64  -> 136 KB
    const int smem1 = 3 * 49152 + 65536;    // C=128 -> 208 KB
    cudaFuncSetAttribute(gram_loss_mma<64, 3>,
                         cudaFuncAttributeMaxDynamicSharedMemorySize, smem0);
    cudaFuncSetAttribute(gram_loss_mma<128, 3>,
                         cudaFuncAttributeMaxDynamicSharedMemorySize, smem1);

    convert_kernel<64><<<dim3(64, 4, 2), 256>>>(fea1_0, fea2_0, 4096, L0_OFF, 1);
    convert_kernel<128><<<dim3(16, 4, 2), 256>>>(fea1_1, fea2_1, 1024, L1_OFF, 0);

    // grids over (tj, ti) tiles of 64(j) x 128(i); early-exit below diagonal
    gram_loss_mma<64, 3><<<dim3(64, 32), 512, smem0>>>(4096, L0_OFF, 0);
    gram_loss_mma<128, 3><<<dim3(16, 8), 512, smem1>>>(1024, L1_OFF, 1);

    finalize_kernel<<<1, 1>>>(out);
}

// round 15
// speedup vs baseline: 1.2213x; 1.2213x over previous
#include <cuda_runtime.h>
#include <cuda_fp16.h>
#include <cstdint>
#include <math.h>

// ============================================================================
// Globals
// ============================================================================

__device__ double g_sum[2];

// fp16 panels (pre-scaled by sqrt(log2e)), [tb = t*4+b][pos][c] layout:
#define L0_OFF 0
#define L1_OFF 2097152
__device__ __half g_scratch[3145728];

// ============================================================================
// Pre-convert: fp32 [b][c][pos] -> fp16 panel [tb][pos][C], scaled by
// sqrt(log2e) so the Gram arrives pre-multiplied by log2(e): softmax exp
// becomes a raw ex2.  (convert<64> also zeroes the global sums.)
// ============================================================================
#define SQRT_LOG2E 1.2011224087f

template <int C>
__global__ void __launch_bounds__(256)
convert_kernel(const float* __restrict__ f1, const float* __restrict__ f2,
               int HW, int off, int do_init)
{
    if (do_init && blockIdx.x == 0 && blockIdx.y == 0 && blockIdx.z == 0 &&
        threadIdx.x == 0) {
        g_sum[0] = 0.0; g_sum[1] = 0.0;
    }
    __shared__ float tile[C * 65];  // [c][pos0..63], padded
    const int t = blockIdx.z, b = blockIdx.y;
    const int pos0 = blockIdx.x * 64;
    const float* src = (t ? f2 : f1) + (size_t)b * C * HW;

    for (int idx = threadIdx.x; idx < C * 64; idx += 256) {
        int c = idx >> 6, p = idx & 63;
        tile[c * 65 + p] = src[(size_t)c * HW + pos0 + p];
    }
    __syncthreads();

    __half* o = g_scratch + off + ((size_t)(t * 4 + b) * HW + pos0) * C;
    constexpr int CSH = (C == 64) ? 6 : 7;
    for (int idx = threadIdx.x; idx < 64 * C; idx += 256) {
        int p = idx >> CSH, c = idx & (C - 1);
        o[(size_t)p * C + c] = __float2half(tile[c * 65 + p] * SQRT_LOG2E);
    }
}

// ============================================================================
// PTX helpers (sm_80+ vocabulary only)
// ============================================================================

__device__ __forceinline__ uint32_t smem_to_u32(const void* p) {
    uint32_t a;
    asm("{ .reg .u64 t; cvta.to.shared.u64 t, %1; cvt.u32.u64 %0, t; }"
        : "=r"(a) : "l"(p));
    return a;
}

__device__ __forceinline__ void ldmatrix_x4(uint32_t* r, uint32_t addr) {
    asm volatile(
        "ldmatrix.sync.aligned.m8n8.x4.shared.b16 {%0,%1,%2,%3}, [%4];"
        : "=r"(r[0]), "=r"(r[1]), "=r"(r[2]), "=r"(r[3]) : "r"(addr));
}

// fp16-accumulate MMA: D (2 regs of half2) += A @ B^T
__device__ __forceinline__ void mma_16816_h(uint32_t* d, const uint32_t* a,
                                            const uint32_t* b) {
    asm volatile(
        "mma.sync.aligned.m16n8k16.row.col.f16.f16.f16.f16 "
        "{%0,%1}, {%2,%3,%4,%5}, {%6,%7}, {%0,%1};"
        : "+r"(d[0]), "+r"(d[1])
        : "r"(a[0]), "r"(a[1]), "r"(a[2]), "r"(a[3]), "r"(b[0]), "r"(b[1]));
}

__device__ __forceinline__ void cp_async16(uint32_t saddr, const void* gaddr) {
    asm volatile("cp.async.cg.shared.global [%0], [%1], 16;"
                 :: "r"(saddr), "l"(gaddr));
}
#define CP_COMMIT() asm volatile("cp.async.commit_group;" ::: "memory")
#define CP_WAIT(n)  asm volatile("cp.async.wait_group %0;" :: "n"(n) : "memory")

__device__ __forceinline__ __half2 u2h(uint32_t v) {
    return *reinterpret_cast<__half2*>(&v);
}
__device__ __forceinline__ uint32_t h2u(__half2 v) {
    return *reinterpret_cast<uint32_t*>(&v);
}

// single-instruction f16x2 2^x
__device__ __forceinline__ __half2 ex2_h2(__half2 x) {
    uint32_t r, xi = h2u(x);
    asm("ex2.approx.f16x2 %0, %1;" : "=r"(r) : "r"(xi));
    return u2h(r);
}

// fast per-element reciprocal of a half2 via 2x rcp.approx.f32
__device__ __forceinline__ __half2 rcp_h2(__half2 s) {
    float lo = __low2float(s), hi = __high2float(s);
    float rlo, rhi;
    asm("rcp.approx.f32 %0, %1;" : "=f"(rlo) : "f"(lo));
    asm("rcp.approx.f32 %0, %1;" : "=f"(rhi) : "f"(hi));
    return __floats2half2_rn(rlo, rhi);
}

// ============================================================================
// Fused Gram (mma.sync fp16 acc) + two-phase f16x2 batch-softmax + |diff|.
// Block: 64(i) x 64(j) tile, triangular 1-D grid (tj >= ti).
// 256 threads = 8 warps (4 row x 2 col), warp = 16m x 32n (R12-proven shape).
// NSTAGES-deep cp.async pipeline over the 8 combos; 2 CTAs/SM both levels.
// ============================================================================
template <int C, int NSTAGES>
__global__ void __launch_bounds__(256, 2)
gram_loss_mma(int HW, int off, int level)
{
    // ---- triangular decode: blockIdx.x -> (ti, tj), tj >= ti ----
    const int k = blockIdx.x;
    int a = (int)((sqrtf(8.0f * k + 1.0f) - 1.0f) * 0.5f);
    while ((a + 1) * (a + 2) / 2 <= k) ++a;
    while (a * (a + 1) / 2 > k) --a;
    const int ti = k - a * (a + 1) / 2;   // 0..a
    const int tj = a;                     // tj >= ti

    constexpr int NCH = C / 8;                 // 16B chunks per row
    constexpr int TILE_B = (C / 64) * 8192;    // 64 rows x 2C bytes
    constexpr int STAGE_B = 2 * TILE_B;        // A | B
    constexpr int KSTEPS = C / 16;
    constexpr int NLOAD = (64 * NCH) / 256;    // cp.async iters per tile/thread

    extern __shared__ char smem[];
    const uint32_t sb = smem_to_u32(smem);
    uint32_t* aff = (uint32_t*)(smem + NSTAGES * STAGE_B);  // [b*8+r][tid] 32 KB

    const int tid = threadIdx.x, wid = tid >> 5, lid = tid & 31;
    const int wrow = wid & 3, wcol = wid >> 2;
    const int i0 = ti * 64, j0 = tj * 64;

    // ---- precomputed loader offsets (combo/stage-invariant) ----
    uint32_t lo_sm[NLOAD];
    uint32_t lo_gl[NLOAD];
    #pragma unroll
    for (int p = 0; p < NLOAD; ++p) {
        const int v = p * 256 + tid;
        const int row = v / NCH, kcq = v % NCH;
        lo_sm[p] = (kcq >> 3) * 8192 + row * 128 +
                   (((kcq & 7) ^ (row & 7)) << 4);
        lo_gl[p] = row * C + kcq * 8;
    }

    const size_t HWC = (size_t)HW * C;
    auto load_stage = [&](int combo, int stage) {
        const __half* base = g_scratch + off + (size_t)combo * HWC;
        const __half* sA = base + (size_t)i0 * C;
        const __half* sB = base + (size_t)j0 * C;
        const uint32_t stb = sb + stage * STAGE_B;
        #pragma unroll
        for (int p = 0; p < NLOAD; ++p) {
            cp_async16(stb + lo_sm[p], sA + lo_gl[p]);
            cp_async16(stb + TILE_B + lo_sm[p], sB + lo_gl[p]);
        }
    };

    // ---- per-lane ldmatrix addressing (stage-invariant) ----
    const int mat = lid >> 3, lrow = lid & 7;
    const int a_row = wrow * 16 + ((mat & 1) << 3) + lrow;
    const int a_kh = mat >> 1;
    const int b_row0 = wcol * 32 + ((mat >> 1) << 3) + lrow;
    const int b_row1 = b_row0 + 16;
    const int b_kh = mat & 1;
    const uint32_t a_off  = a_row * 128;
    const uint32_t b_off0 = TILE_B + b_row0 * 128;
    const uint32_t b_off1 = TILE_B + b_row1 * 128;
    const int a_r7 = a_row & 7, b_r70 = b_row0 & 7, b_r71 = b_row1 & 7;

    // ---- preload NSTAGES-1 combos ----
    #pragma unroll
    for (int pc = 0; pc < NSTAGES - 1; ++pc) {
        load_stage(pc, pc); CP_COMMIT();
    }

    // acc[b][r]: r = mi*2 + dreg; mi: 0=(h0,nb0) 1=(h0,nb1) 2=(h1,nb0) 3=(h1,nb1)
    // dreg 0 -> row gi, 1 -> row gi+8; each reg = half2 over cols (j, j+1)
    uint32_t acc[4][8];
    float wsum = 0.0f;
    const bool fullabove = (tj > ti);
    const int gi = lid >> 2, gj = (lid & 3) << 1;

    #pragma unroll 1
    for (int t = 0; t < 2; ++t) {
        #pragma unroll
        for (int b = 0; b < 4; ++b) {
            const int combo = t * 4 + b;
            // wait until stage `combo` is complete: allow at most
            // min(NSTAGES-2, 7-combo) newer groups to remain pending
            if (NSTAGES >= 4) {
                if (combo <= 5)      { CP_WAIT(2); }
                else if (combo == 6) { CP_WAIT(1); }
                else                 { CP_WAIT(0); }
            } else {
                CP_WAIT(0);
            }
            __syncthreads();  // combo's stage ready; prior readers done
            if (combo + NSTAGES - 1 < 8) {
                load_stage(combo + NSTAGES - 1, (combo + NSTAGES - 1) % NSTAGES);
                CP_COMMIT();
            }

            const uint32_t stb = sb + (combo % NSTAGES) * STAGE_B;
            #pragma unroll
            for (int s = 0; s < 8; ++s) acc[b][s] = 0u;

            #pragma unroll
            for (int ks = 0; ks < KSTEPS; ++ks) {
                const int kb = ks >> 2, kc = (ks & 3) * 2;
                uint32_t af[4], b0[4], b1[4];
                ldmatrix_x4(af, stb + a_off  + kb * 8192 +
                                (((kc + a_kh) ^ a_r7)  << 4));
                ldmatrix_x4(b0, stb + b_off0 + kb * 8192 +
                                (((kc + b_kh) ^ b_r70) << 4));
                ldmatrix_x4(b1, stb + b_off1 + kb * 8192 +
                                (((kc + b_kh) ^ b_r71) << 4));
                mma_16816_h(acc[b] + 0, af, b0 + 0);   // h0 nb0 -> r0,r1
                mma_16816_h(acc[b] + 2, af, b0 + 2);   // h0 nb1 -> r2,r3
                mma_16816_h(acc[b] + 4, af, b1 + 0);   // h1 nb0 -> r4,r5
                mma_16816_h(acc[b] + 6, af, b1 + 2);   // h1 nb1 -> r6,r7
            }
        }

        // ---- per-phase f16x2 epilogue: base-2 softmax + |diff| ----
        #pragma unroll
        for (int r = 0; r < 8; ++r) {
            const __half2 A0 = u2h(acc[0][r]), A1 = u2h(acc[1][r]);
            const __half2 A2 = u2h(acc[2][r]), A3 = u2h(acc[3][r]);
            const __half2 m = __hmax2(__hmax2(A0, A1), __hmax2(A2, A3));
            const __half2 e0 = ex2_h2(__hsub2(A0, m));
            const __half2 e1 = ex2_h2(__hsub2(A1, m));
            const __half2 e2 = ex2_h2(__hsub2(A2, m));
            const __half2 e3 = ex2_h2(__hsub2(A3, m));
            const __half2 sum = __hadd2(__hadd2(e0, e1), __hadd2(e2, e3));
            const __half2 inv = rcp_h2(sum);
            const __half2 p0 = __hmul2(e0, inv), p1 = __hmul2(e1, inv);
            const __half2 p2 = __hmul2(e2, inv), p3 = __hmul2(e3, inv);

            if (t == 0) {
                aff[(0 * 8 + r) * 256 + tid] = h2u(p0);
                aff[(1 * 8 + r) * 256 + tid] = h2u(p1);
                aff[(2 * 8 + r) * 256 + tid] = h2u(p2);
                aff[(3 * 8 + r) * 256 + tid] = h2u(p3);
            } else {
                __half2 d = __habs2(__hsub2(u2h(aff[(0*8+r)*256 + tid]), p0));
                d = __hadd2(d, __habs2(__hsub2(u2h(aff[(1*8+r)*256 + tid]), p1)));
                d = __hadd2(d, __habs2(__hsub2(u2h(aff[(2*8+r)*256 + tid]), p2)));
                d = __hadd2(d, __habs2(__hsub2(u2h(aff[(3*8+r)*256 + tid]), p3)));
                const float2 dd = __half22float2(d);
                if (fullabove) {
                    wsum += dd.x + dd.y;
                } else {
                    const int mi = r >> 1;
                    const int i = i0 + wrow * 16 + gi + ((r & 1) << 3);
                    const int j = j0 + wcol * 32 + ((mi >> 1) << 4)
                                + ((mi & 1) << 3) + gj;
                    const float wlo = (j > i) ? 2.0f : ((j == i) ? 1.0f : 0.0f);
                    const float whi = (j + 1 > i) ? 2.0f : ((j + 1 == i) ? 1.0f : 0.0f);
                    wsum += wlo * dd.x + whi * dd.y;
                }
            }
        }
    }

    // ---- reduce: warp shfl -> smem -> single atomic ----
    if (fullabove) wsum *= 2.0f;
    #pragma unroll
    for (int s2 = 16; s2; s2 >>= 1) wsum += __shfl_xor_sync(0xFFFFFFFFu, wsum, s2);
    __syncthreads();
    float* wsums = (float*)smem;
    if (lid == 0) wsums[wid] = wsum;
    __syncthreads();
    if (tid == 0) {
        float tt = 0.0f;
        #pragma unroll
        for (int wq = 0; wq < 8; ++wq) tt += wsums[wq];
        atomicAdd(&g_sum[level], (double)tt);
    }
}

__global__ void finalize_kernel(float* out) {
    const double n0 = 4.0 * 4096.0 * 4096.0;
    const double n1 = 4.0 * 1024.0 * 1024.0;
    out[0] = (float)((g_sum[0] / n0 + g_sum[1] / n1) * 0.5);
}

// ============================================================================
// Launch
// ============================================================================
extern "C" void kernel_launch(void* const* d_in, const int* in_sizes, int n_in,
                              void* d_out, int out_size)
{
    const float* fea1_0 = (const float*)d_in[0];  // (4, 64, 64, 64)
    const float* fea1_1 = (const float*)d_in[1];  // (4, 128, 32, 32)
    const float* fea2_0 = (const float*)d_in[2];
    const float* fea2_1 = (const float*)d_in[3];
    float* out = (float*)d_out;

    // smem: NSTAGES * stage + 32KB aff buffer -> 96 KB both levels, 2 CTAs/SM
    const int smem0 = 4 * 16384 + 32768;    // C=64,  4 stages
    const int smem1 = 2 * 32768 + 32768;    // C=128, 2 stages
    cudaFuncSetAttribute(gram_loss_mma<64, 4>,
                         cudaFuncAttributeMaxDynamicSharedMemorySize, smem0);
    cudaFuncSetAttribute(gram_loss_mma<128, 2>,
                         cudaFuncAttributeMaxDynamicSharedMemorySize, smem1);

    convert_kernel<64><<<dim3(64, 4, 2), 256>>>(fea1_0, fea2_0, 4096, L0_OFF, 1);
    convert_kernel<128><<<dim3(16, 4, 2), 256>>>(fea1_1, fea2_1, 1024, L1_OFF, 0);

    // triangular grids: T*(T+1)/2 blocks of 64x64
    gram_loss_mma<64, 4><<<64 * 65 / 2, 256, smem0>>>(4096, L0_OFF, 0);   // 2080
    gram_loss_mma<128, 2><<<16 * 17 / 2, 256, smem1>>>(1024, L1_OFF, 1);  // 136

    finalize_kernel<<<1, 1>>>(out);
}

// round 16
// speedup vs baseline: 1.3556x; 1.1099x over previous
#include <cuda_runtime.h>
#include <cuda_fp16.h>
#include <cstdint>
#include <math.h>

// ============================================================================
// Globals
// ============================================================================

__device__ double g_sum[2];

// fp16 panels (pre-scaled by sqrt(log2e)), [tb = t*4+b][pos][c] layout:
#define L0_OFF 0
#define L1_OFF 2097152
__device__ __half g_scratch[3145728];

#define SQRT_LOG2E 1.2011224087f

// ============================================================================
// Pre-convert body: fp32 [b][c][pos] -> fp16 panel [tb][pos][C] * sqrt(log2e)
// ============================================================================
template <int C>
__device__ __forceinline__ void convert_body(
    const float* __restrict__ f1, const float* __restrict__ f2,
    int HW, int off, int bx, float* tile)
{
    const int t = blockIdx.z, b = blockIdx.y;
    const int pos0 = bx * 64;
    const float* src = (t ? f2 : f1) + (size_t)b * C * HW;

    for (int idx = threadIdx.x; idx < C * 64; idx += 256) {
        int c = idx >> 6, p = idx & 63;
        tile[c * 65 + p] = src[(size_t)c * HW + pos0 + p];
    }
    __syncthreads();

    __half* o = g_scratch + off + ((size_t)(t * 4 + b) * HW + pos0) * C;
    constexpr int CSH = (C == 64) ? 6 : 7;
    for (int idx = threadIdx.x; idx < 64 * C; idx += 256) {
        int p = idx >> CSH, c = idx & (C - 1);
        o[(size_t)p * C + c] = __float2half(tile[c * 65 + p] * SQRT_LOG2E);
    }
}

__global__ void __launch_bounds__(256)
convert_fused(const float* __restrict__ f1_0, const float* __restrict__ f2_0,
              const float* __restrict__ f1_1, const float* __restrict__ f2_1)
{
    if (blockIdx.x == 0 && blockIdx.y == 0 && blockIdx.z == 0 &&
        threadIdx.x == 0) {
        g_sum[0] = 0.0; g_sum[1] = 0.0;
    }
    __shared__ float tile[128 * 65];
    if (blockIdx.x < 64)
        convert_body<64>(f1_0, f2_0, 4096, L0_OFF, blockIdx.x, tile);
    else
        convert_body<128>(f1_1, f2_1, 1024, L1_OFF, blockIdx.x - 64, tile);
}

// ============================================================================
// PTX helpers (sm_80+ vocabulary only)
// ============================================================================

__device__ __forceinline__ uint32_t smem_to_u32(const void* p) {
    uint32_t a;
    asm("{ .reg .u64 t; cvta.to.shared.u64 t, %1; cvt.u32.u64 %0, t; }"
        : "=r"(a) : "l"(p));
    return a;
}

__device__ __forceinline__ void ldmatrix_x4(uint32_t* r, uint32_t addr) {
    asm volatile(
        "ldmatrix.sync.aligned.m8n8.x4.shared.b16 {%0,%1,%2,%3}, [%4];"
        : "=r"(r[0]), "=r"(r[1]), "=r"(r[2]), "=r"(r[3]) : "r"(addr));
}

// fp16-accumulate MMA: D (2 regs of half2) += A @ B^T
__device__ __forceinline__ void mma_16816_h(uint32_t* d, const uint32_t* a,
                                            const uint32_t* b) {
    asm volatile(
        "mma.sync.aligned.m16n8k16.row.col.f16.f16.f16.f16 "
        "{%0,%1}, {%2,%3,%4,%5}, {%6,%7}, {%0,%1};"
        : "+r"(d[0]), "+r"(d[1])
        : "r"(a[0]), "r"(a[1]), "r"(a[2]), "r"(a[3]), "r"(b[0]), "r"(b[1]));
}

__device__ __forceinline__ void cp_async16(uint32_t saddr, const void* gaddr) {
    asm volatile("cp.async.cg.shared.global [%0], [%1], 16;"
                 :: "r"(saddr), "l"(gaddr));
}
#define CP_COMMIT() asm volatile("cp.async.commit_group;" ::: "memory")
#define CP_WAIT(n)  asm volatile("cp.async.wait_group %0;" :: "n"(n) : "memory")

__device__ __forceinline__ __half2 u2h(uint32_t v) {
    return *reinterpret_cast<__half2*>(&v);
}
__device__ __forceinline__ uint32_t h2u(__half2 v) {
    return *reinterpret_cast<uint32_t*>(&v);
}

// single-instruction f16x2 2^x
__device__ __forceinline__ __half2 ex2_h2(__half2 x) {
    uint32_t r, xi = h2u(x);
    asm("ex2.approx.f16x2 %0, %1;" : "=r"(r) : "r"(xi));
    return u2h(r);
}

// fast per-element reciprocal of a half2 via 2x rcp.approx.f32
__device__ __forceinline__ __half2 rcp_h2(__half2 s) {
    float lo = __low2float(s), hi = __high2float(s);
    float rlo, rhi;
    asm("rcp.approx.f32 %0, %1;" : "=f"(rlo) : "f"(lo));
    asm("rcp.approx.f32 %0, %1;" : "=f"(rhi) : "f"(hi));
    return __floats2half2_rn(rlo, rhi);
}

// ============================================================================
// Fused Gram body (mma.sync fp16 acc) + two-phase f16x2 softmax + |diff|.
// 64x64 tile, triangular index k; 8 warps (4x2), warp 16m x 32n.
// ============================================================================
template <int C, int NSTAGES>
__device__ __forceinline__ void gram_body(int k, int HW, int off, int level,
                                          char* smem)
{
    // ---- triangular decode: k -> (ti, tj), tj >= ti ----
    int a = (int)((sqrtf(8.0f * k + 1.0f) - 1.0f) * 0.5f);
    while ((a + 1) * (a + 2) / 2 <= k) ++a;
    while (a * (a + 1) / 2 > k) --a;
    const int ti = k - a * (a + 1) / 2;   // 0..a
    const int tj = a;                     // tj >= ti

    constexpr int NCH = C / 8;                 // 16B chunks per row
    constexpr int TILE_B = (C / 64) * 8192;    // 64 rows x 2C bytes
    constexpr int STAGE_B = 2 * TILE_B;        // A | B
    constexpr int KSTEPS = C / 16;
    constexpr int NLOAD = (64 * NCH) / 256;    // cp.async iters per tile/thread

    const uint32_t sb = smem_to_u32(smem);
    uint32_t* aff = (uint32_t*)(smem + NSTAGES * STAGE_B);  // [b*8+r][tid] 32 KB

    const int tid = threadIdx.x, wid = tid >> 5, lid = tid & 31;
    const int wrow = wid & 3, wcol = wid >> 2;
    const int i0 = ti * 64, j0 = tj * 64;

    // ---- precomputed loader offsets (combo/stage-invariant) ----
    uint32_t lo_sm[NLOAD];
    uint32_t lo_gl[NLOAD];
    #pragma unroll
    for (int p = 0; p < NLOAD; ++p) {
        const int v = p * 256 + tid;
        const int row = v / NCH, kcq = v % NCH;
        lo_sm[p] = (kcq >> 3) * 8192 + row * 128 +
                   (((kcq & 7) ^ (row & 7)) << 4);
        lo_gl[p] = row * C + kcq * 8;
    }

    const size_t HWC = (size_t)HW * C;
    auto load_stage = [&](int combo, int stage) {
        const __half* base = g_scratch + off + (size_t)combo * HWC;
        const __half* sA = base + (size_t)i0 * C;
        const __half* sB = base + (size_t)j0 * C;
        const uint32_t stb = sb + stage * STAGE_B;
        #pragma unroll
        for (int p = 0; p < NLOAD; ++p) {
            cp_async16(stb + lo_sm[p], sA + lo_gl[p]);
            cp_async16(stb + TILE_B + lo_sm[p], sB + lo_gl[p]);
        }
    };

    // ---- per-lane ldmatrix addressing (stage-invariant) ----
    const int mat = lid >> 3, lrow = lid & 7;
    const int a_row = wrow * 16 + ((mat & 1) << 3) + lrow;
    const int a_kh = mat >> 1;
    const int b_row0 = wcol * 32 + ((mat >> 1) << 3) + lrow;
    const int b_row1 = b_row0 + 16;
    const int b_kh = mat & 1;
    const uint32_t a_off  = a_row * 128;
    const uint32_t b_off0 = TILE_B + b_row0 * 128;
    const uint32_t b_off1 = TILE_B + b_row1 * 128;
    const int a_r7 = a_row & 7, b_r70 = b_row0 & 7, b_r71 = b_row1 & 7;

    // ---- preload NSTAGES-1 combos ----
    #pragma unroll
    for (int pc = 0; pc < NSTAGES - 1; ++pc) {
        load_stage(pc, pc); CP_COMMIT();
    }

    uint32_t acc[4][8];
    float wsum = 0.0f;
    const bool fullabove = (tj > ti);
    const int gi = lid >> 2, gj = (lid & 3) << 1;

    #pragma unroll 1
    for (int t = 0; t < 2; ++t) {
        #pragma unroll
        for (int b = 0; b < 4; ++b) {
            const int combo = t * 4 + b;
            if (NSTAGES >= 4) {
                if (combo <= 5)      { CP_WAIT(2); }
                else if (combo == 6) { CP_WAIT(1); }
                else                 { CP_WAIT(0); }
            } else {
                CP_WAIT(0);
            }
            __syncthreads();  // combo's stage ready; prior readers done
            if (combo + NSTAGES - 1 < 8) {
                load_stage(combo + NSTAGES - 1, (combo + NSTAGES - 1) % NSTAGES);
                CP_COMMIT();
            }

            const uint32_t stb = sb + (combo % NSTAGES) * STAGE_B;
            #pragma unroll
            for (int s = 0; s < 8; ++s) acc[b][s] = 0u;

            #pragma unroll
            for (int ks = 0; ks < KSTEPS; ++ks) {
                const int kb = ks >> 2, kc = (ks & 3) * 2;
                uint32_t af[4], b0[4], b1[4];
                ldmatrix_x4(af, stb + a_off  + kb * 8192 +
                                (((kc + a_kh) ^ a_r7)  << 4));
                ldmatrix_x4(b0, stb + b_off0 + kb * 8192 +
                                (((kc + b_kh) ^ b_r70) << 4));
                ldmatrix_x4(b1, stb + b_off1 + kb * 8192 +
                                (((kc + b_kh) ^ b_r71) << 4));
                mma_16816_h(acc[b] + 0, af, b0 + 0);   // h0 nb0 -> r0,r1
                mma_16816_h(acc[b] + 2, af, b0 + 2);   // h0 nb1 -> r2,r3
                mma_16816_h(acc[b] + 4, af, b1 + 0);   // h1 nb0 -> r4,r5
                mma_16816_h(acc[b] + 6, af, b1 + 2);   // h1 nb1 -> r6,r7
            }
        }

        // ---- per-phase f16x2 epilogue: base-2 softmax + |diff| ----
        #pragma unroll
        for (int r = 0; r < 8; ++r) {
            const __half2 A0 = u2h(acc[0][r]), A1 = u2h(acc[1][r]);
            const __half2 A2 = u2h(acc[2][r]), A3 = u2h(acc[3][r]);
            const __half2 m = __hmax2(__hmax2(A0, A1), __hmax2(A2, A3));
            const __half2 e0 = ex2_h2(__hsub2(A0, m));
            const __half2 e1 = ex2_h2(__hsub2(A1, m));
            const __half2 e2 = ex2_h2(__hsub2(A2, m));
            const __half2 e3 = ex2_h2(__hsub2(A3, m));
            const __half2 sum = __hadd2(__hadd2(e0, e1), __hadd2(e2, e3));
            const __half2 inv = rcp_h2(sum);
            const __half2 p0 = __hmul2(e0, inv), p1 = __hmul2(e1, inv);
            const __half2 p2 = __hmul2(e2, inv), p3 = __hmul2(e3, inv);

            if (t == 0) {
                aff[(0 * 8 + r) * 256 + tid] = h2u(p0);
                aff[(1 * 8 + r) * 256 + tid] = h2u(p1);
                aff[(2 * 8 + r) * 256 + tid] = h2u(p2);
                aff[(3 * 8 + r) * 256 + tid] = h2u(p3);
            } else {
                __half2 d = __habs2(__hsub2(u2h(aff[(0*8+r)*256 + tid]), p0));
                d = __hadd2(d, __habs2(__hsub2(u2h(aff[(1*8+r)*256 + tid]), p1)));
                d = __hadd2(d, __habs2(__hsub2(u2h(aff[(2*8+r)*256 + tid]), p2)));
                d = __hadd2(d, __habs2(__hsub2(u2h(aff[(3*8+r)*256 + tid]), p3)));
                const float2 dd = __half22float2(d);
                if (fullabove) {
                    wsum += dd.x + dd.y;
                } else {
                    const int mi = r >> 1;
                    const int i = i0 + wrow * 16 + gi + ((r & 1) << 3);
                    const int j = j0 + wcol * 32 + ((mi >> 1) << 4)
                                + ((mi & 1) << 3) + gj;
                    const float wlo = (j > i) ? 2.0f : ((j == i) ? 1.0f : 0.0f);
                    const float whi = (j + 1 > i) ? 2.0f : ((j + 1 == i) ? 1.0f : 0.0f);
                    wsum += wlo * dd.x + whi * dd.y;
                }
            }
        }
    }

    // ---- reduce: warp shfl -> smem -> single atomic ----
    if (fullabove) wsum *= 2.0f;
    #pragma unroll
    for (int s2 = 16; s2; s2 >>= 1) wsum += __shfl_xor_sync(0xFFFFFFFFu, wsum, s2);
    __syncthreads();
    float* wsums = (float*)smem;
    if (lid == 0) wsums[wid] = wsum;
    __syncthreads();
    if (tid == 0) {
        float tt = 0.0f;
        #pragma unroll
        for (int wq = 0; wq < 8; ++wq) tt += wsums[wq];
        atomicAdd(&g_sum[level], (double)tt);
    }
}

// Combined launch: first N_L1 blocks run the heavier C=128 tiles (scheduled
// early so the 2080 small C=64 blocks pack around them), rest run C=64.
#define N_L1 136
#define N_L0 2080

__global__ void __launch_bounds__(256, 2)
gram_fused()
{
    extern __shared__ char smem[];
    if (blockIdx.x < N_L1)
        gram_body<128, 2>(blockIdx.x, 1024, L1_OFF, 1, smem);
    else
        gram_body<64, 4>(blockIdx.x - N_L1, 4096, L0_OFF, 0, smem);
}

__global__ void finalize_kernel(float* out) {
    const double n0 = 4.0 * 4096.0 * 4096.0;
    const double n1 = 4.0 * 1024.0 * 1024.0;
    out[0] = (float)((g_sum[0] / n0 + g_sum[1] / n1) * 0.5);
}

// ============================================================================
// Launch
// ============================================================================
extern "C" void kernel_launch(void* const* d_in, const int* in_sizes, int n_in,
                              void* d_out, int out_size)
{
    const float* fea1_0 = (const float*)d_in[0];  // (4, 64, 64, 64)
    const float* fea1_1 = (const float*)d_in[1];  // (4, 128, 32, 32)
    const float* fea2_0 = (const float*)d_in[2];
    const float* fea2_1 = (const float*)d_in[3];
    float* out = (float*)d_out;

    // smem: both bodies use exactly 96 KB -> 2 CTAs/SM
    const int smem_bytes = 98304;
    cudaFuncSetAttribute(gram_fused,
                         cudaFuncAttributeMaxDynamicSharedMemorySize, smem_bytes);

    convert_fused<<<dim3(80, 4, 2), 256>>>(fea1_0, fea2_0, fea1_1, fea2_1);

    gram_fused<<<N_L0 + N_L1, 256, smem_bytes>>>();

    finalize_kernel<<<1, 1>>>(out);
}